// round 17
// baseline (speedup 1.0000x reference)
#include <cuda_runtime.h>
#include <cuda_fp16.h>
#include <math.h>
#include <cstdint>

#define SQ   2048
#define HID  2048
#define NHK  16
#define KDIM 128
#define VDIM 256
#define NVD  4096
#define OUT_ELEMS  (SQ*HID)
#define SF_ELEMS   (NHK*KDIM*VDIM)

// ---------------- scratch -----------------------------------------------------
__device__ __align__(256) float g_v   [SQ*NVD];
__device__ __align__(256) float g_qc  [SQ*HID];
__device__ __align__(256) float g_kc  [SQ*HID];
__device__ __align__(256) float g_gate[SQ*NHK];
__device__ __align__(256) float g_beta[SQ*NHK];
__device__ __align__(256) float g_part[2*SQ*NVD];   // partial scan outputs

__device__ __align__(256) __half g_xh [SQ*HID];
__device__ __align__(256) __half g_wqh[HID*HID];
__device__ __align__(256) __half g_wkh[HID*HID];
__device__ __align__(256) __half g_wvh[NVD*HID];
__device__ __align__(256) __half g_woh[HID*NVD];
__device__ __align__(256) __half g_ah [SQ*NVD];
__device__ __align__(256) __half g_qph[SQ*HID];
__device__ __align__(256) __half g_kph[SQ*HID];
__device__ __align__(256) __half g_cqh[HID*512];
__device__ __align__(256) __half g_ckh[HID*512];

// ---------------- PTX helpers --------------------------------------------------
__device__ __forceinline__ uint32_t smem_u32(const void* p) {
    uint32_t a;
    asm("{ .reg .u64 t; cvta.to.shared.u64 t, %1; cvt.u32.u64 %0, t; }" : "=r"(a) : "l"(p));
    return a;
}
__device__ __forceinline__ void cp16(uint32_t dst, const void* src) {
    asm volatile("cp.async.cg.shared.global [%0], [%1], 16;" :: "r"(dst), "l"(src));
}
#define CP_COMMIT() asm volatile("cp.async.commit_group;")
#define CP_WAIT(n)  asm volatile("cp.async.wait_group %0;" :: "n"(n))

__device__ __forceinline__ void ldsm_x4(uint32_t& r0, uint32_t& r1, uint32_t& r2,
                                        uint32_t& r3, uint32_t a) {
    asm volatile("ldmatrix.sync.aligned.m8n8.x4.shared.b16 {%0,%1,%2,%3}, [%4];"
                 : "=r"(r0), "=r"(r1), "=r"(r2), "=r"(r3) : "r"(a));
}
__device__ __forceinline__ void mma16816(float* d, const uint32_t* a, const uint32_t* b) {
    asm volatile(
        "mma.sync.aligned.m16n8k16.row.col.f32.f16.f16.f32 "
        "{%0,%1,%2,%3},{%4,%5,%6,%7},{%8,%9},{%0,%1,%2,%3};"
        : "+f"(d[0]), "+f"(d[1]), "+f"(d[2]), "+f"(d[3])
        : "r"(a[0]), "r"(a[1]), "r"(a[2]), "r"(a[3]), "r"(b[0]), "r"(b[1]));
}

// ---------------- mega split + gates kernel -----------------------------------
__device__ __forceinline__ void half_one(const float2* X, __half2* H, int i) {
    float2 x = X[i];
    __half2 h;
    h.x = __float2half_rn(x.x);
    h.y = __float2half_rn(x.y);
    H[i] = h;
}

// blocks: x 8192 | wq 8192 | wk 8192 | wv 16384 | wo 16384 | convq 4096 |
//         convk 4096 | gates 2048  (total 67584)
__global__ __launch_bounds__(256) void split_all(
        const float* xf, const float2* wq, const float2* wk,
        const float2* wv, const float2* wo,
        const float* cwq, const float* cwk,
        const float* Wg, const float* bg, const float* Wb, const float* bb,
        float* gate, float* beta) {
    __shared__ float xs[HID];
    int b = blockIdx.x;
    int tid = threadIdx.x;
    if (b < 8192) {
        half_one((const float2*)xf, (__half2*)g_xh, b * 256 + tid);
    } else if (b < 16384) {
        half_one(wq, (__half2*)g_wqh, (b - 8192) * 256 + tid);
    } else if (b < 24576) {
        half_one(wk, (__half2*)g_wkh, (b - 16384) * 256 + tid);
    } else if (b < 40960) {
        half_one(wv, (__half2*)g_wvh, (b - 24576) * 256 + tid);
    } else if (b < 57344) {
        half_one(wo, (__half2*)g_woh, (b - 40960) * 256 + tid);
    } else if (b < 61440) {
        int e = (b - 57344) * 256 + tid;
        int o = e >> 9, kk = e & 511, tap = kk >> 7, i = kk & 127;
        g_cqh[e] = __float2half_rn(cwq[o * 512 + i * 4 + tap]);
    } else if (b < 65536) {
        int e = (b - 61440) * 256 + tid;
        int o = e >> 9, kk = e & 511, tap = kk >> 7, i = kk & 127;
        g_ckh[e] = __float2half_rn(cwk[o * 512 + i * 4 + tap]);
    } else {
        int s = b - 65536;
        for (int i = tid; i < HID; i += 256) xs[i] = xf[(size_t)s * HID + i];
        __syncthreads();
        int w = tid >> 5, lane = tid & 31;
#pragma unroll
        for (int j = 0; j < 4; ++j) {
            int r = w * 4 + j;
            const float* row = (r < 16) ? (Wg + (size_t)r * HID)
                                        : (Wb + (size_t)(r - 16) * HID);
            float p = 0.f;
            for (int i = lane; i < HID; i += 32) p += xs[i] * row[i];
#pragma unroll
            for (int off = 16; off; off >>= 1) p += __shfl_xor_sync(0xffffffffu, p, off);
            if (lane == 0) {
                float bv = (r < 16) ? bg[r] : bb[r - 16];
                float sv = 1.f / (1.f + expf(-(p + bv)));
                if (r < 16) gate[s * NHK + r] = sv;
                else        beta[s * NHK + r - 16] = sv;
            }
        }
    }
}

// ---------------- common GEMM pieces ------------------------------------------
#define MATB  8192u
#define STGB  (2u*MATB)      // 16384
#define GSMEM (3u*STGB)      // 49152

__device__ __forceinline__ uint32_t sw64(uint32_t row, uint32_t c) {
    return row * 64u + ((c ^ ((row >> 1) & 3u)) << 4);
}

__device__ __forceinline__ void ld_stage(uint32_t st,
        const __half* __restrict__ A, const __half* __restrict__ B,
        int bm, int bn, int k0, int K, int t) {
#pragma unroll
    for (int i = 0; i < 4; ++i) {
        int idx = t + i * 256;
        int mat = idx >> 9;
        int j   = idx & 511;
        int row = j >> 2, c = j & 3;
        const __half* base = mat ? B : A;
        int grow = (mat ? bn : bm) + row;
        cp16(st + mat * MATB + sw64(row, c),
             base + (size_t)grow * K + k0 + c * 8);
    }
}

__device__ __forceinline__ void chunk_compute(uint32_t stg, int lane, int wm, int wn,
                                              float acc[4][4][4]) {
    const uint32_t rA0 = (uint32_t)wm * 64 + (lane & 15);
    const uint32_t hiA = (uint32_t)lane >> 4;
    const uint32_t sA  = (rA0 >> 1) & 3u;
    const uint32_t rB0 = (uint32_t)wn * 32 + (((uint32_t)lane >> 4) << 3) + (lane & 7);
    const uint32_t hB  = ((uint32_t)lane >> 3) & 1u;
    const uint32_t sB  = (rB0 >> 1) & 3u;
    const uint32_t baseA = stg + rA0 * 64;
    const uint32_t baseB = stg + MATB + rB0 * 64;
#pragma unroll
    for (int kh = 0; kh < 2; ++kh) {
        const uint32_t cA = (((uint32_t)(kh * 2) + hiA) ^ sA) << 4;
        const uint32_t cB = (((uint32_t)(kh * 2) + hB) ^ sB) << 4;
        uint32_t a[4][4], b[4][2];
#pragma unroll
        for (int mt = 0; mt < 4; ++mt)
            ldsm_x4(a[mt][0], a[mt][1], a[mt][2], a[mt][3],
                    baseA + mt * 1024 + cA);
#pragma unroll
        for (int p = 0; p < 2; ++p)
            ldsm_x4(b[2*p][0], b[2*p][1], b[2*p+1][0], b[2*p+1][1],
                    baseB + p * 1024 + cB);
#pragma unroll
        for (int mt = 0; mt < 4; ++mt)
#pragma unroll
            for (int nt = 0; nt < 4; ++nt)
                mma16816(acc[mt][nt], a[mt], b[nt]);
    }
}

// ---------------- fused q/k/v projection --------------------------------------
__global__ __launch_bounds__(256, 2) void proj_fused(
        __half* __restrict__ Qp, __half* __restrict__ Kp, float* __restrict__ V) {
    extern __shared__ char smem[];
    uint32_t sb = smem_u32(smem);
    const int t = threadIdx.x, wid = t >> 5, lane = t & 31;
    const int wm = wid >> 2, wn = wid & 3;

    int bx = blockIdx.x;
    int which, bm, bn;
    const __half* B_;
    if (bx < 256)      { which = 0; bm = (bx >> 4) << 7;          bn = (bx & 15) << 7; B_ = g_wqh; }
    else if (bx < 512) { which = 1; int i = bx - 256; bm = (i >> 4) << 7; bn = (i & 15) << 7; B_ = g_wkh; }
    else               { which = 2; int i = bx - 512; bm = (i >> 5) << 7; bn = (i & 31) << 7; B_ = g_wvh; }

    float acc[4][4][4];
#pragma unroll
    for (int mt = 0; mt < 4; ++mt)
#pragma unroll
        for (int nt = 0; nt < 4; ++nt)
#pragma unroll
            for (int r = 0; r < 4; ++r) acc[mt][nt][r] = 0.f;

    const int nch = HID / 32;
    ld_stage(sb,        g_xh, B_, bm, bn, 0,  HID, t); CP_COMMIT();
    ld_stage(sb + STGB, g_xh, B_, bm, bn, 32, HID, t); CP_COMMIT();
    for (int c = 0; c < nch; ++c) {
        if (c + 1 < nch) { CP_WAIT(1); } else { CP_WAIT(0); }
        __syncthreads();
        if (c + 2 < nch) {
            ld_stage(sb + ((c + 2) % 3) * STGB, g_xh, B_, bm, bn, (c + 2) * 32, HID, t);
            CP_COMMIT();
        }
        chunk_compute(sb + (c % 3) * STGB, lane, wm, wn, acc);
    }

    const int r0 = bm + wm * 64 + (lane >> 2);
    const int ccl = wn * 32 + (lane & 3) * 2;
    if (which < 2) {
        __half* Ch = which ? Kp : Qp;
#pragma unroll
        for (int mt = 0; mt < 4; ++mt)
#pragma unroll
            for (int nt = 0; nt < 4; ++nt)
#pragma unroll
                for (int half = 0; half < 2; ++half) {
                    int rr = r0 + mt * 16 + half * 8;
                    int cl = bn + ccl + nt * 8;
                    __half2 h;
                    h.x = __float2half_rn(acc[mt][nt][half * 2 + 0]);
                    h.y = __float2half_rn(acc[mt][nt][half * 2 + 1]);
                    ((__half2*)Ch)[((size_t)rr * HID + cl) >> 1] = h;
                }
    } else {
#pragma unroll
        for (int mt = 0; mt < 4; ++mt)
#pragma unroll
            for (int nt = 0; nt < 4; ++nt) {
                int rr = r0 + mt * 16;
                int cl = bn + ccl + nt * 8;
                *(float2*)&V[(size_t)rr * NVD + cl]       = make_float2(acc[mt][nt][0], acc[mt][nt][1]);
                *(float2*)&V[(size_t)(rr + 8) * NVD + cl] = make_float2(acc[mt][nt][2], acc[mt][nt][3]);
            }
    }
}

// ---------------- output projection -------------------------------------------
__global__ __launch_bounds__(256, 2) void gemm_mma(
        const __half* __restrict__ A, const __half* __restrict__ B,
        float* __restrict__ C, int M, int N, int K) {
    extern __shared__ char smem[];
    uint32_t sb = smem_u32(smem);
    const int t = threadIdx.x, wid = t >> 5, lane = t & 31;
    const int wm = wid >> 2, wn = wid & 3;
    const int bm = blockIdx.y * 128, bn = blockIdx.x * 128;

    float acc[4][4][4];
#pragma unroll
    for (int mt = 0; mt < 4; ++mt)
#pragma unroll
        for (int nt = 0; nt < 4; ++nt)
#pragma unroll
            for (int r = 0; r < 4; ++r) acc[mt][nt][r] = 0.f;

    const int nch = K / 32;
    ld_stage(sb,        A, B, bm, bn, 0,  K, t); CP_COMMIT();
    ld_stage(sb + STGB, A, B, bm, bn, 32, K, t); CP_COMMIT();
    for (int c = 0; c < nch; ++c) {
        if (c + 1 < nch) { CP_WAIT(1); } else { CP_WAIT(0); }
        __syncthreads();
        if (c + 2 < nch) {
            ld_stage(sb + ((c + 2) % 3) * STGB, A, B, bm, bn, (c + 2) * 32, K, t);
            CP_COMMIT();
        }
        chunk_compute(sb + (c % 3) * STGB, lane, wm, wn, acc);
    }

    const int r0 = bm + wm * 64 + (lane >> 2);
    const int cc = bn + wn * 32 + (lane & 3) * 2;
#pragma unroll
    for (int mt = 0; mt < 4; ++mt)
#pragma unroll
        for (int nt = 0; nt < 4; ++nt) {
            int rr = r0 + mt * 16;
            int cl = cc + nt * 8;
            *(float2*)&C[(size_t)rr * N + cl]       = make_float2(acc[mt][nt][0], acc[mt][nt][1]);
            *(float2*)&C[(size_t)(rr + 8) * N + cl] = make_float2(acc[mt][nt][2], acc[mt][nt][3]);
        }
}

// ---------------- conv via fp16 mma -------------------------------------------
__global__ __launch_bounds__(256, 2) void conv_mma(
        const float* __restrict__ bq, const float* __restrict__ bk,
        float* __restrict__ Yq, float* __restrict__ Yk) {
    extern __shared__ char smem[];
    uint32_t sb = smem_u32(smem);
    const int t = threadIdx.x, wid = t >> 5, lane = t & 31;
    const int wm = wid >> 2, wn = wid & 3;
    const int g  = blockIdx.x;
    const int bm = blockIdx.y * 128;
    const int cz = blockIdx.z;
    const __half* X = cz ? g_kph : g_qph;
    const __half* B = cz ? g_ckh : g_cqh;
    const float* bias = cz ? bk : bq;
    float* Y = cz ? Yk : Yq;

    float acc[4][4][4];
#pragma unroll
    for (int mt = 0; mt < 4; ++mt)
#pragma unroll
        for (int nt = 0; nt < 4; ++nt)
#pragma unroll
            for (int r = 0; r < 4; ++r) acc[mt][nt][r] = 0.f;

    auto load_chunk = [&](uint32_t st, int k0) {
        int tap = k0 >> 7, i0 = k0 & 127;
#pragma unroll
        for (int i = 0; i < 4; ++i) {
            int idx = t + i * 256;
            int mat = idx >> 9;
            int j   = idx & 511;
            int row = j >> 2, c = j & 3;
            uint32_t dst = st + mat * MATB + sw64(row, c);
            if (mat == 0) {
                int s = bm + row - 3 + tap;
                if (s >= 0)
                    cp16(dst, X + (size_t)s * HID + g * 128 + i0 + c * 8);
                else
                    *(uint4*)(smem + (dst - sb)) = make_uint4(0, 0, 0, 0);
            } else {
                cp16(dst, B + (size_t)(g * 128 + row) * 512 + k0 + c * 8);
            }
        }
    };

    const int nch = 16;
    load_chunk(sb, 0);         CP_COMMIT();
    load_chunk(sb + STGB, 32); CP_COMMIT();
    for (int c = 0; c < nch; ++c) {
        if (c + 1 < nch) { CP_WAIT(1); } else { CP_WAIT(0); }
        __syncthreads();
        if (c + 2 < nch) {
            load_chunk(sb + ((c + 2) % 3) * STGB, (c + 2) * 32);
            CP_COMMIT();
        }
        chunk_compute(sb + (c % 3) * STGB, lane, wm, wn, acc);
    }

    const int r0 = bm + wm * 64 + (lane >> 2);
    const int c0 = wn * 32 + (lane & 3) * 2;
#pragma unroll
    for (int mt = 0; mt < 4; ++mt)
#pragma unroll
        for (int nt = 0; nt < 4; ++nt) {
            int cl = c0 + nt * 8;
            float b0 = bias[g * 128 + cl], b1 = bias[g * 128 + cl + 1];
#pragma unroll
            for (int half = 0; half < 2; ++half) {
                int rr = r0 + mt * 16 + half * 8;
                float y0 = acc[mt][nt][half * 2 + 0] + b0;
                float y1 = acc[mt][nt][half * 2 + 1] + b1;
                y0 = y0 / (1.f + expf(-y0));
                y1 = y1 / (1.f + expf(-y1));
                *(float2*)&Y[(size_t)rr * HID + g * 128 + cl] = make_float2(y0, y1);
            }
        }
}

// ---------------- row-split gated scan (vectorized smem layout) ---------------
// 256 CTAs: h (16) x row-half rh (2) x col-group (8 of 32 cols).
// q/k stored permuted: col c -> float index f(c) = ((c&7)|((c>>5)<<3))*4 + ((c>>3)&3)
// so thread rg's 8 rows {8a+rg} live in 2 float4 granules (rg and rg+8).
__global__ __launch_bounds__(256) void scan_kernel(const float* __restrict__ Q,
        const float* __restrict__ K, const float* __restrict__ V,
        const float* __restrict__ Beta, float* __restrict__ P,
        float* __restrict__ Sf) {
    __shared__ __align__(16) float qs[32][64];
    __shared__ __align__(16) float ks[32][64];
    __shared__ float vs[32][32];
    __shared__ float bs[32];
    const int h  = blockIdx.x >> 4;
    const int rh = (blockIdx.x >> 3) & 1;
    const int c0 = (blockIdx.x & 7) * 32;
    const int t  = threadIdx.x;
    const int rg = t & 7;
    const int cg = t >> 3;

    float S[8];
#pragma unroll
    for (int a = 0; a < 8; ++a) S[a] = 0.f;

    float* Pr = P + (size_t)rh * SQ * NVD;

    for (int s0 = 0; s0 < SQ; s0 += 32) {
        for (int idx = t; idx < 32 * 64; idx += 256) {
            int tt = idx >> 6, col = idx & 63;
            int f = (((col & 7) | ((col >> 5) << 3)) << 2) | ((col >> 3) & 3);
            size_t g = (size_t)(s0 + tt) * HID + h * 128 + rh * 64 + col;
            qs[tt][f] = Q[g];
            ks[tt][f] = K[g];
        }
        for (int idx = t; idx < 32 * 32; idx += 256) {
            int tt = idx >> 5, col = idx & 31;
            vs[tt][col] = V[(size_t)(s0 + tt) * NVD + h * 256 + c0 + col];
        }
        if (t < 32) bs[t] = Beta[(s0 + t) * NHK + h];
        __syncthreads();
        for (int tt = 0; tt < 32; ++tt) {
            float bt = bs[tt];
            float v  = vs[tt][cg];
            float4 k0 = *(const float4*)&ks[tt][rg * 4];
            float4 k1 = *(const float4*)&ks[tt][(rg + 8) * 4];
            float4 q0 = *(const float4*)&qs[tt][rg * 4];
            float4 q1 = *(const float4*)&qs[tt][(rg + 8) * 4];
            float p;
            S[0] = bt * S[0] + k0.x * v;  p  = q0.x * S[0];
            S[1] = bt * S[1] + k0.y * v;  p += q0.y * S[1];
            S[2] = bt * S[2] + k0.z * v;  p += q0.z * S[2];
            S[3] = bt * S[3] + k0.w * v;  p += q0.w * S[3];
            S[4] = bt * S[4] + k1.x * v;  p += q1.x * S[4];
            S[5] = bt * S[5] + k1.y * v;  p += q1.y * S[5];
            S[6] = bt * S[6] + k1.z * v;  p += q1.z * S[6];
            S[7] = bt * S[7] + k1.w * v;  p += q1.w * S[7];
#pragma unroll
            for (int off = 4; off; off >>= 1)
                p += __shfl_xor_sync(0xffffffffu, p, off);
            if (rg == 0)
                Pr[(size_t)(s0 + tt) * NVD + h * 256 + c0 + cg] = p;
        }
        __syncthreads();
    }
    if (Sf != nullptr) {
#pragma unroll
        for (int a = 0; a < 8; ++a)
            Sf[(size_t)h * KDIM * VDIM + (size_t)(rh * 64 + rg + 8 * a) * VDIM
               + c0 + cg] = S[a];
    }
}

// combine: O = gate * (P0 + P1), fp16
__global__ __launch_bounds__(256) void combine_kernel(const float* __restrict__ P,
        const float* __restrict__ Gate, __half* __restrict__ O) {
    int i2 = blockIdx.x * 256 + threadIdx.x;
    int idx = i2 * 2;
    int s = idx >> 12;
    int col = idx & 4095;
    int h = col >> 8;
    float g = Gate[s * NHK + h];
    float2 a = *(const float2*)&P[idx];
    float2 b = *(const float2*)&P[SQ * (size_t)NVD + idx];
    __half2 hv;
    hv.x = __float2half_rn(g * (a.x + b.x));
    hv.y = __float2half_rn(g * (a.y + b.y));
    ((__half2*)O)[i2] = hv;
}

// ---------------- launch ------------------------------------------------------
extern "C" void kernel_launch(void* const* d_in, const int* in_sizes, int n_in,
                              void* d_out, int out_size) {
    const float* x   = (const float*)d_in[0];
    const float* Wq  = (const float*)d_in[1];
    const float* Wk  = (const float*)d_in[2];
    const float* Wv  = (const float*)d_in[3];
    const float* Wo  = (const float*)d_in[4];
    const float* Wqc = (const float*)d_in[5];
    const float* bqc = (const float*)d_in[6];
    const float* Wkc = (const float*)d_in[7];
    const float* bkc = (const float*)d_in[8];
    const float* Wg  = (const float*)d_in[9];
    const float* bg  = (const float*)d_in[10];
    const float* Wb  = (const float*)d_in[11];
    const float* bb  = (const float*)d_in[12];
    float* out = (float*)d_out;

    float *dv, *dqc, *dkc, *dgate, *dbeta, *dpart;
    cudaGetSymbolAddress((void**)&dv,    g_v);
    cudaGetSymbolAddress((void**)&dqc,   g_qc);
    cudaGetSymbolAddress((void**)&dkc,   g_kc);
    cudaGetSymbolAddress((void**)&dgate, g_gate);
    cudaGetSymbolAddress((void**)&dbeta, g_beta);
    cudaGetSymbolAddress((void**)&dpart, g_part);

    __half *ah, *woh, *qph, *kph;
    cudaGetSymbolAddress((void**)&ah,  g_ah);
    cudaGetSymbolAddress((void**)&woh, g_woh);
    cudaGetSymbolAddress((void**)&qph, g_qph);
    cudaGetSymbolAddress((void**)&kph, g_kph);

    cudaFuncSetAttribute(proj_fused, cudaFuncAttributeMaxDynamicSharedMemorySize, GSMEM);
    cudaFuncSetAttribute(gemm_mma,   cudaFuncAttributeMaxDynamicSharedMemorySize, GSMEM);
    cudaFuncSetAttribute(conv_mma,   cudaFuncAttributeMaxDynamicSharedMemorySize, GSMEM);

    dim3 blk(256);
    // 0: mega split + gates
    split_all<<<67584, blk>>>(x, (const float2*)Wq, (const float2*)Wk,
                              (const float2*)Wv, (const float2*)Wo, Wqc, Wkc,
                              Wg, bg, Wb, bb, dgate, dbeta);
    // 1: fused q/k/v projections
    proj_fused<<<1024, blk, GSMEM>>>(qph, kph, dv);
    // 2: both convs
    conv_mma<<<dim3(16, 16, 2), blk, GSMEM>>>(bqc, bkc, dqc, dkc);
    // 3: row-split scan (profiled launch)
    float* Sf = (out_size >= OUT_ELEMS + SF_ELEMS) ? (out + OUT_ELEMS) : nullptr;
    scan_kernel<<<256, blk>>>(dqc, dkc, dv, dbeta, dpart, Sf);
    // 4: combine partials + gate -> fp16
    combine_kernel<<<SQ * NVD / 512, blk>>>(dpart, dgate, ah);
    // 5: output projection
    gemm_mma<<<dim3(HID/128, SQ/128), blk, GSMEM>>>(ah, woh, out, SQ, HID, NVD);
}